// round 15
// baseline (speedup 1.0000x reference)
#include <cuda_runtime.h>
#include <math.h>

// A[b,i,j] = softmax_i(s_i + s_j + bias) = exp(s_i)/sum_i' exp(s_i')
// (s_j and bias cancel under softmax over axis=1). Output row (b,i,:) is a
// constant p[b,i] broadcast N wide.
//
// TWO launches:
//  K1: dot+exp (4 rows/warp, MLP=8); per-batch sum accumulated as FIXED-POINT
//      integer atomics (order-independent -> bitwise deterministic).
//  K2: EXACT R3-champion fill shape: 1 row/block, head = 2 scalar ldgs
//      (isum[b] is a 32B array, L2/L1-resident chip-wide), 16 regs, no smem,
//      no syncthreads, __stcs streaming stores.
//      Replay reset: modular arrival counter; the LAST K2 block (arrives after
//      all blocks have read isum) zeroes it for the next graph replay.

#define MAX_BN   16384    // B*N for B=4, N=4096
#define K1_THREADS 256    // 8 warps * 4 rows = 32 rows/block
#define ROWS_PER_WARP 4
#define MAX_B    16
#define FXSCALE  274877906944.0   // 2^38

__device__ float               g_e[MAX_BN];      // exp(s)
__device__ unsigned long long  g_isum[MAX_B];    // fixed-point batch sums (zero-init)
__device__ unsigned int        g_ctr;            // monotonic arrival counter (wrap-safe)

// ---- K1: dot + exp + fixed-point atomic batch sum ----
__global__ void __launch_bounds__(K1_THREADS)
dot_exp_kernel(const float* __restrict__ h,
               const float* __restrict__ w,
               int BN, int D4, int N) {
    __shared__ float s_warp[K1_THREADS / 32];

    const int warp = threadIdx.x >> 5;
    const int lane = threadIdx.x & 31;
    const int rows_per_block = (K1_THREADS / 32) * ROWS_PER_WARP;
    const int row0 = blockIdx.x * rows_per_block + warp * ROWS_PER_WARP;

    const float4* wv = reinterpret_cast<const float4*>(w);
    float e_sum = 0.0f;

    if (D4 == 64 && row0 + ROWS_PER_WARP <= BN) {
        float4 b0 = __ldg(wv + lane);
        float4 b1 = __ldg(wv + lane + 32);
        // batch all 8 h loads up front (MLP=8)
        float4 a0[ROWS_PER_WARP], a1[ROWS_PER_WARP];
        #pragma unroll
        for (int r = 0; r < ROWS_PER_WARP; r++) {
            const float4* hr = reinterpret_cast<const float4*>(h) + (size_t)(row0 + r) * 64;
            a0[r] = __ldg(hr + lane);
            a1[r] = __ldg(hr + lane + 32);
        }
        #pragma unroll
        for (int r = 0; r < ROWS_PER_WARP; r++) {
            float acc = a0[r].x * b0.x + a0[r].y * b0.y + a0[r].z * b0.z + a0[r].w * b0.w
                      + a1[r].x * b1.x + a1[r].y * b1.y + a1[r].z * b1.z + a1[r].w * b1.w;
            #pragma unroll
            for (int o = 16; o; o >>= 1)
                acc += __shfl_xor_sync(0xFFFFFFFFu, acc, o);
            float ev = __expf(acc);
            if (lane == 0) {
                g_e[row0 + r] = ev;
                e_sum += ev;                 // sequential in r: deterministic
            }
        }
    } else {
        for (int r = 0; r < ROWS_PER_WARP; r++) {
            int row = row0 + r;
            if (row >= BN) break;
            const float4* hr = reinterpret_cast<const float4*>(h) + (size_t)row * D4;
            float acc = 0.0f;
            for (int c = lane; c < D4; c += 32) {
                float4 a = __ldg(hr + c);
                float4 b = __ldg(wv + c);
                acc += a.x * b.x + a.y * b.y + a.z * b.z + a.w * b.w;
            }
            #pragma unroll
            for (int o = 16; o; o >>= 1)
                acc += __shfl_xor_sync(0xFFFFFFFFu, acc, o);
            if (lane == 0) {
                float ev = __expf(acc);
                g_e[row] = ev;
                e_sum += ev;
            }
        }
    }

    if (lane == 0) s_warp[warp] = e_sum;
    __syncthreads();
    if (threadIdx.x == 0) {
        float p = 0.0f;
        #pragma unroll
        for (int i = 0; i < K1_THREADS / 32; i++) p += s_warp[i];  // fixed order
        // fixed-point: integer atomic add is order-independent -> deterministic
        unsigned long long fx = (unsigned long long)((double)p * FXSCALE);
        int batch = (blockIdx.x * rows_per_block) / N;   // block covers one batch
        atomicAdd(&g_isum[batch], fx);
    }
}

// ---- K2: R3-champion headless fill + end-of-kernel state reset ----
__global__ void __launch_bounds__(256)
fill_kernel(const float* __restrict__ e,
            float4* __restrict__ out,
            int N4, int B, unsigned int total_blocks) {
    size_t row = (size_t)blockIdx.y * gridDim.x + blockIdx.x;

    // head: one u64 ldg (32B array, L1-hot) + one f32 ldg, then stream
    double sum = (double)__ldg(&g_isum[blockIdx.y]) * (1.0 / FXSCALE);
    float v = (float)((double)__ldg(&e[row]) / sum);
    float4 v4 = make_float4(v, v, v, v);

    float4* o = out + row * (size_t)N4;
    #pragma unroll 4
    for (int c = threadIdx.x; c < N4; c += blockDim.x)
        __stcs(&o[c], v4);

    // replay reset: last-arriving block zeroes isum. All blocks incremented
    // AFTER their read of isum, so the last arrival implies all reads done.
    // total_blocks divides 2^32 -> modular test survives counter wrap.
    if (threadIdx.x == 0) {
        __threadfence();
        unsigned int a = atomicAdd(&g_ctr, 1u);
        if (a % total_blocks == total_blocks - 1u) {
            for (int b = 0; b < B; b++) g_isum[b] = 0ull;
        }
    }
}

extern "C" void kernel_launch(void* const* d_in, const int* in_sizes, int n_in,
                              void* d_out, int out_size) {
    const float* h = (const float*)d_in[0];
    const float* w = (const float*)d_in[1];
    // d_in[2] (bias) cancels in the softmax over axis=1 -> unused.

    int D  = in_sizes[1];                       // 256
    int BN = in_sizes[0] / D;                   // B*N = 16384
    int N  = (int)((long long)out_size / BN);   // 4096
    int B  = BN / N;                            // 4

    float* e = nullptr;
    cudaGetSymbolAddress((void**)&e, g_e);

    int rows_per_block = (K1_THREADS / 32) * ROWS_PER_WARP;     // 32
    int k1_blocks = (BN + rows_per_block - 1) / rows_per_block; // 512
    dot_exp_kernel<<<k1_blocks, K1_THREADS>>>(h, w, BN, D >> 2, N);

    dim3 grid(N, B);                                            // 4096 x 4
    fill_kernel<<<grid, 256>>>(e, (float4*)d_out, N >> 2, B, (unsigned)(N * B));
}

// round 16
// speedup vs baseline: 2.3169x; 2.3169x over previous
#include <cuda_runtime.h>
#include <math.h>

// A[b,i,j] = softmax_i(s_i + s_j + bias) = exp(s_i)/sum_i' exp(s_i')
// (s_j and bias cancel under softmax over axis=1). Output row (b,i,:) is a
// constant p[b,i] broadcast N wide.
//
// CHAMPION (R8, 43.49us; reproduced R13 43.78us): TWO launches.
//  K1: dot+exp (4 rows/warp, MLP=8) + per-block partial sums (no atomics)
//  K2: fill — 8 rows/block, 512 thr, smem inv head, interleaved 8-stream
//      __stcs store loop. All fp32 (R15 lesson: per-thread FP64 = disaster;
//      post-store __threadfence breaks store pipelining).

#define MAX_BN   16384    // B*N for B=4, N=4096
#define K1_THREADS 256    // 8 warps * 4 rows = 32 rows/block
#define ROWS_PER_WARP 4
#define MAX_PART  1024
#define FILL_ROWS 8       // rows per fill block
#define FILL_THREADS 512

__device__ float g_e[MAX_BN];        // exp(s)
__device__ float g_part[MAX_PART];   // per-block partial sums

// ---- K1: dot + exp + block partial sum ----
__global__ void __launch_bounds__(K1_THREADS)
dot_exp_kernel(const float* __restrict__ h,
               const float* __restrict__ w,
               int BN, int D4) {
    __shared__ float s_warp[K1_THREADS / 32];

    const int warp = threadIdx.x >> 5;
    const int lane = threadIdx.x & 31;
    const int row0 = blockIdx.x * (K1_THREADS / 32 * ROWS_PER_WARP) + warp * ROWS_PER_WARP;

    const float4* wv = reinterpret_cast<const float4*>(w);
    float e_sum = 0.0f;

    if (D4 == 64 && row0 + ROWS_PER_WARP <= BN) {
        float4 b0 = __ldg(wv + lane);
        float4 b1 = __ldg(wv + lane + 32);
        // batch all 8 h loads up front (MLP=8)
        float4 a0[ROWS_PER_WARP], a1[ROWS_PER_WARP];
        #pragma unroll
        for (int r = 0; r < ROWS_PER_WARP; r++) {
            const float4* hr = reinterpret_cast<const float4*>(h) + (size_t)(row0 + r) * 64;
            a0[r] = __ldg(hr + lane);
            a1[r] = __ldg(hr + lane + 32);
        }
        #pragma unroll
        for (int r = 0; r < ROWS_PER_WARP; r++) {
            float acc = a0[r].x * b0.x + a0[r].y * b0.y + a0[r].z * b0.z + a0[r].w * b0.w
                      + a1[r].x * b1.x + a1[r].y * b1.y + a1[r].z * b1.z + a1[r].w * b1.w;
            #pragma unroll
            for (int o = 16; o; o >>= 1)
                acc += __shfl_xor_sync(0xFFFFFFFFu, acc, o);
            float ev = __expf(acc);
            if (lane == 0) {
                g_e[row0 + r] = ev;
                e_sum += ev;                 // sequential in r: deterministic
            }
        }
    } else {
        for (int r = 0; r < ROWS_PER_WARP; r++) {
            int row = row0 + r;
            if (row >= BN) break;
            const float4* hr = reinterpret_cast<const float4*>(h) + (size_t)row * D4;
            float acc = 0.0f;
            for (int c = lane; c < D4; c += 32) {
                float4 a = __ldg(hr + c);
                float4 b = __ldg(wv + c);
                acc += a.x * b.x + a.y * b.y + a.z * b.z + a.w * b.w;
            }
            #pragma unroll
            for (int o = 16; o; o >>= 1)
                acc += __shfl_xor_sync(0xFFFFFFFFu, acc, o);
            if (lane == 0) {
                float ev = __expf(acc);
                g_e[row] = ev;
                e_sum += ev;
            }
        }
    }

    if (lane == 0) s_warp[warp] = e_sum;
    __syncthreads();
    if (threadIdx.x == 0) {
        float p = 0.0f;
        #pragma unroll
        for (int i = 0; i < K1_THREADS / 32; i++) p += s_warp[i];  // fixed order
        g_part[blockIdx.x] = p;
    }
}

// ---- K2: per-block inv reduce (amortized over 8 rows) + interleaved fill ----
__global__ void __launch_bounds__(FILL_THREADS)
fill_kernel(const float* __restrict__ e,
            float4* __restrict__ out,
            int N4, int parts_per_batch) {
    __shared__ float inv_s;
    __shared__ float v_s[FILL_ROWS];

    const int tid = threadIdx.x;

    // warp 0: reduce this batch's partials in FIXED order (identical on every
    // block of the batch -> deterministic & consistent)
    if (tid < 32) {
        int base = blockIdx.y * parts_per_batch;
        int per_lane = parts_per_batch >> 5;          // 128/32 = 4
        float p = 0.0f;
        for (int k = 0; k < per_lane; k++)
            p += g_part[base + tid * per_lane + k];   // sequential per lane
        #pragma unroll
        for (int o = 16; o; o >>= 1)
            p += __shfl_xor_sync(0xFFFFFFFFu, p, o);
        if (tid == 0) inv_s = 1.0f / p;
    }
    __syncthreads();

    size_t row0 = (size_t)blockIdx.y * ((size_t)gridDim.x * FILL_ROWS)
                + (size_t)blockIdx.x * FILL_ROWS;
    if (tid < FILL_ROWS)
        v_s[tid] = __ldg(&e[row0 + tid]) * inv_s;
    __syncthreads();

    // interleaved 8-stream store loop (champion shape)
    float4* o = out + row0 * (size_t)N4;
    #pragma unroll
    for (int c = tid; c < N4; c += FILL_THREADS) {
        #pragma unroll
        for (int r = 0; r < FILL_ROWS; r++) {
            float v = v_s[r];
            __stcs(o + (size_t)r * N4 + c, make_float4(v, v, v, v));
        }
    }
}

extern "C" void kernel_launch(void* const* d_in, const int* in_sizes, int n_in,
                              void* d_out, int out_size) {
    const float* h = (const float*)d_in[0];
    const float* w = (const float*)d_in[1];
    // d_in[2] (bias) cancels in the softmax over axis=1 -> unused.

    int D  = in_sizes[1];                       // 256
    int BN = in_sizes[0] / D;                   // B*N = 16384
    int N  = (int)((long long)out_size / BN);   // 4096
    int B  = BN / N;                            // 4

    float* e = nullptr;
    cudaGetSymbolAddress((void**)&e, g_e);

    int rows_per_block = (K1_THREADS / 32) * ROWS_PER_WARP;     // 32
    int k1_blocks = (BN + rows_per_block - 1) / rows_per_block; // 512
    dot_exp_kernel<<<k1_blocks, K1_THREADS>>>(h, w, BN, D >> 2);

    int parts_per_batch = k1_blocks / B;                        // 128
    dim3 grid(N / FILL_ROWS, B);                                // 512 x 4
    fill_kernel<<<grid, FILL_THREADS>>>(e, (float4*)d_out, N >> 2, parts_per_batch);
}

// round 17
// speedup vs baseline: 2.3358x; 1.0082x over previous
#include <cuda_runtime.h>
#include <math.h>

// A[b,i,j] = softmax_i(s_i + s_j + bias) = exp(s_i)/sum_i' exp(s_i')
// (s_j and bias cancel under softmax over axis=1). Output row (b,i,:) is a
// constant p[b,i] broadcast N wide.
//
// TWO launches, HEADLESS 1-row fill (the only shape ever measured at 38.7us):
//  K1: dot+exp (4 rows/warp, MLP=8); batch sums accumulated as FIXED-POINT
//      u64 atomics (order-independent -> bitwise deterministic, R15's good idea).
//  K2: grid (N,B), 1 row/block, 256 thr. Per-thread independent head:
//      u64 ldg (L1-hot) + cvt + fast fp32 div — no smem, no syncthreads,
//      no FP64 (R15's fatal mistake), no fences. __stcs streaming stores.
//      Replay reset via modular arrival counter, fence-free.

#define MAX_BN   16384    // B*N for B=4, N=4096
#define K1_THREADS 256    // 8 warps * 4 rows = 32 rows/block
#define ROWS_PER_WARP 4
#define MAX_B    16
#define FXSCALE  274877906944.0f   // 2^38

__device__ float              g_e[MAX_BN];     // exp(s)
__device__ unsigned long long g_isum[MAX_B];   // fixed-point batch sums (zero-init)
__device__ unsigned int       g_ctr;           // monotonic arrival counter

// ---- K1: dot + exp + fixed-point atomic batch sum ----
__global__ void __launch_bounds__(K1_THREADS)
dot_exp_kernel(const float* __restrict__ h,
               const float* __restrict__ w,
               int BN, int D4, int N) {
    __shared__ float s_warp[K1_THREADS / 32];

    const int warp = threadIdx.x >> 5;
    const int lane = threadIdx.x & 31;
    const int rows_per_block = (K1_THREADS / 32) * ROWS_PER_WARP;
    const int row0 = blockIdx.x * rows_per_block + warp * ROWS_PER_WARP;

    const float4* wv = reinterpret_cast<const float4*>(w);
    float e_sum = 0.0f;

    if (D4 == 64 && row0 + ROWS_PER_WARP <= BN) {
        float4 b0 = __ldg(wv + lane);
        float4 b1 = __ldg(wv + lane + 32);
        // batch all 8 h loads up front (MLP=8)
        float4 a0[ROWS_PER_WARP], a1[ROWS_PER_WARP];
        #pragma unroll
        for (int r = 0; r < ROWS_PER_WARP; r++) {
            const float4* hr = reinterpret_cast<const float4*>(h) + (size_t)(row0 + r) * 64;
            a0[r] = __ldg(hr + lane);
            a1[r] = __ldg(hr + lane + 32);
        }
        #pragma unroll
        for (int r = 0; r < ROWS_PER_WARP; r++) {
            float acc = a0[r].x * b0.x + a0[r].y * b0.y + a0[r].z * b0.z + a0[r].w * b0.w
                      + a1[r].x * b1.x + a1[r].y * b1.y + a1[r].z * b1.z + a1[r].w * b1.w;
            #pragma unroll
            for (int o = 16; o; o >>= 1)
                acc += __shfl_xor_sync(0xFFFFFFFFu, acc, o);
            float ev = __expf(acc);
            if (lane == 0) {
                g_e[row0 + r] = ev;
                e_sum += ev;                 // sequential in r: deterministic
            }
        }
    } else {
        for (int r = 0; r < ROWS_PER_WARP; r++) {
            int row = row0 + r;
            if (row >= BN) break;
            const float4* hr = reinterpret_cast<const float4*>(h) + (size_t)row * D4;
            float acc = 0.0f;
            for (int c = lane; c < D4; c += 32) {
                float4 a = __ldg(hr + c);
                float4 b = __ldg(wv + c);
                acc += a.x * b.x + a.y * b.y + a.z * b.z + a.w * b.w;
            }
            #pragma unroll
            for (int o = 16; o; o >>= 1)
                acc += __shfl_xor_sync(0xFFFFFFFFu, acc, o);
            if (lane == 0) {
                float ev = __expf(acc);
                g_e[row] = ev;
                e_sum += ev;
            }
        }
    }

    if (lane == 0) s_warp[warp] = e_sum;
    __syncthreads();
    if (threadIdx.x == 0) {
        float p = 0.0f;
        #pragma unroll
        for (int i = 0; i < K1_THREADS / 32; i++) p += s_warp[i];  // fixed order
        // fixed-point u64 atomic: order-independent -> bitwise deterministic
        unsigned long long fx = (unsigned long long)((double)p * (double)FXSCALE);
        int batch = (blockIdx.x * rows_per_block) / N;   // block covers one batch
        atomicAdd(&g_isum[batch], fx);
    }
}

// ---- K2: headless 1-row fill (R3 shape) + fence-free replay reset ----
__global__ void __launch_bounds__(256)
fill_kernel(const float* __restrict__ e,
            float4* __restrict__ out,
            int N4, int B, unsigned int total_blocks) {
    size_t row = (size_t)blockIdx.y * gridDim.x + blockIdx.x;

    // per-thread independent head: all fp32, ~30cyc, overlaps the e[row] load
    float sum_f = (float)__ldg(&g_isum[blockIdx.y]) * (1.0f / FXSCALE);
    float v = __fdividef(__ldg(&e[row]), sum_f);
    float4 v4 = make_float4(v, v, v, v);

    float4* o = out + row * (size_t)N4;
    #pragma unroll 4
    for (int c = threadIdx.x; c < N4; c += blockDim.x)
        __stcs(&o[c], v4);

    // replay reset: last-arriving block zeroes isum. The counter increment
    // data-depends on v (which consumed the isum load), so every block's
    // isum READ precedes its increment. No fences; the kernel boundary
    // publishes the reset to next replay's K1. total_blocks divides 2^32.
    if (threadIdx.x == 0) {
        unsigned int dep = __float_as_uint(v) & 0u;        // forces v -> ctr dependency
        unsigned int a = atomicAdd(&g_ctr, 1u + dep);
        if (a % total_blocks == total_blocks - 1u) {
            for (int b = 0; b < B; b++) g_isum[b] = 0ull;
        }
    }
}

extern "C" void kernel_launch(void* const* d_in, const int* in_sizes, int n_in,
                              void* d_out, int out_size) {
    const float* h = (const float*)d_in[0];
    const float* w = (const float*)d_in[1];
    // d_in[2] (bias) cancels in the softmax over axis=1 -> unused.

    int D  = in_sizes[1];                       // 256
    int BN = in_sizes[0] / D;                   // B*N = 16384
    int N  = (int)((long long)out_size / BN);   // 4096
    int B  = BN / N;                            // 4

    float* e = nullptr;
    cudaGetSymbolAddress((void**)&e, g_e);

    int rows_per_block = (K1_THREADS / 32) * ROWS_PER_WARP;     // 32
    int k1_blocks = (BN + rows_per_block - 1) / rows_per_block; // 512
    dot_exp_kernel<<<k1_blocks, K1_THREADS>>>(h, w, BN, D >> 2, N);

    dim3 grid(N, B);                                            // 4096 x 4
    fill_kernel<<<grid, 256>>>(e, (float4*)d_out, N >> 2, B, (unsigned)(N * B));
}